// round 9
// baseline (speedup 1.0000x reference)
#include <cuda_runtime.h>
#include <cuda_bf16.h>

#define N_NODES 100000
#define D 32
#define ELL_W 64   // max in-degree; deg ~ Poisson(16), P(>=64) ~ 1e-17 per node

// ------------------------- scratch (__device__ globals) --------------------
__device__ float g_pre[N_NODES * D];        // root @ Wr + b (per layer)
__device__ float g_h1[N_NODES * D];         // layer-1 output
__device__ int   g_cnt[N_NODES];            // per-node fill cursor == in-degree
__device__ int   g_ell[N_NODES * ELL_W];    // ELL src-index table

// ---------------------------------------------------------------------------
// Edge-parallel ELL fill, 2 edges per thread (independent chains).
__global__ void ell_fill_kernel(const int* __restrict__ src,
                                const int* __restrict__ dst,
                                int* __restrict__ cnt,
                                int* __restrict__ ell, int E) {
    int t = blockIdx.x * blockDim.x + threadIdx.x;
    int e0 = t * 2;
    if (e0 + 1 < E) {
        int2 s = *reinterpret_cast<const int2*>(src + e0);
        int2 d = *reinterpret_cast<const int2*>(dst + e0);
        int slot0 = atomicAdd(&cnt[d.x], 1);
        int slot1 = atomicAdd(&cnt[d.y], 1);
        if (slot0 < ELL_W) ell[d.x * ELL_W + slot0] = s.x;
        if (slot1 < ELL_W) ell[d.y * ELL_W + slot1] = s.y;
    } else if (e0 < E) {
        int sv = src[e0], dv = dst[e0];
        int slot = atomicAdd(&cnt[dv], 1);
        if (slot < ELL_W) ell[dv * ELL_W + slot] = sv;
    }
}

// ---------------------------------------------------------------------------
// Root GEMV: pre[n] = root[n] @ Wr + b   (no relu; consumed by fused kernel)
__global__ void rootmv_kernel(const float* __restrict__ root,
                              const float* __restrict__ Wr,
                              const float* __restrict__ b,
                              float* __restrict__ pre, int n) {
    int lane = threadIdx.x & 31;
    int w = blockIdx.x * (blockDim.x >> 5) + (threadIdx.x >> 5);
    int nWarps = gridDim.x * (blockDim.x >> 5);

    float wr[D];
#pragma unroll
    for (int k = 0; k < D; k++) wr[k] = Wr[k * D + lane];
    float bias = b[lane];

    for (int node = w; node < n; node += nWarps) {
        const float4* rp = reinterpret_cast<const float4*>(root + (size_t)node * D);
        float acc = bias;
#pragma unroll
        for (int q = 0; q < D / 4; q++) {
            float4 r = rp[q];   // uniform address -> broadcast LDG.128
            acc = fmaf(r.x, wr[4 * q + 0], acc);
            acc = fmaf(r.y, wr[4 * q + 1], acc);
            acc = fmaf(r.z, wr[4 * q + 2], acc);
            acc = fmaf(r.w, wr[4 * q + 3], acc);
        }
        pre[(size_t)node * D + lane] = acc;
    }
}

// ---------------------------------------------------------------------------
// Fused gather + mean@Wl + pre + relu. TWO nodes per warp-iteration,
// grid-stride over node pairs (amortizes the Wl register preload).
// Gather phase is the proven R8 scheme; mean rows are staged in 256B smem and
// consumed as uniform LDS.128 broadcasts with lane = output column.
__global__ void __launch_bounds__(256) fused_kernel(
        const float* __restrict__ x,
        const int* __restrict__ cnt,
        const int* __restrict__ ell,
        const float* __restrict__ Wl,
        const float* __restrict__ pre,
        float* __restrict__ out, int n) {
    __shared__ float sm[8][2][D];   // [warp][node-in-pair][col]

    int lane = threadIdx.x & 31;
    int wIn = threadIdx.x >> 5;
    int warp = blockIdx.x * 8 + wIn;
    int nWarps = gridDim.x * 8;
    int nPairs = (n + 1) >> 1;

    int egrp = lane >> 3;   // 0..3 : edge within a 4-edge chunk
    int cgrp = lane & 7;    // 0..7 : float4 column group

    // Wl column in registers (lane = output column)
    float wl[D];
#pragma unroll
    for (int k = 0; k < D; k++) wl[k] = Wl[k * D + lane];

    for (int p = warp; p < nPairs; p += nWarps) {
        int node0 = p * 2;
        int node1 = node0 + 1;
        bool has1 = (node1 < n);

        int deg0 = cnt[node0];
        int deg1 = has1 ? cnt[node1] : 0;
        int m0 = deg0 < ELL_W ? deg0 : ELL_W;
        int m1 = deg1 < ELL_W ? deg1 : ELL_W;
        const int* row0 = ell + node0 * ELL_W;
        const int* row1 = ell + node1 * ELL_W;

        int id0[8], id1[8];
#pragma unroll
        for (int c = 0; c < 8; c++) {
            int e = c * 4 + egrp;
            id0[c] = (e < m0) ? row0[e] : -1;
            id1[c] = (has1 && e < m1) ? row1[e] : -1;
        }

        float4 acc0 = make_float4(0.f, 0.f, 0.f, 0.f);
        float4 acc1 = make_float4(0.f, 0.f, 0.f, 0.f);
#pragma unroll
        for (int c = 0; c < 8; c++) {
            if (id0[c] >= 0) {
                float4 v = *reinterpret_cast<const float4*>(
                    x + (size_t)id0[c] * D + cgrp * 4);
                acc0.x += v.x; acc0.y += v.y; acc0.z += v.z; acc0.w += v.w;
            }
            if (id1[c] >= 0) {
                float4 v = *reinterpret_cast<const float4*>(
                    x + (size_t)id1[c] * D + cgrp * 4);
                acc1.x += v.x; acc1.y += v.y; acc1.z += v.z; acc1.w += v.w;
            }
        }
        if (m0 > 32 || m1 > 32) {   // rare tail: deg > 32
#pragma unroll
            for (int c = 0; c < 8; c++) {
                int e = 32 + c * 4 + egrp;
                if (e < m0) {
                    float4 v = *reinterpret_cast<const float4*>(
                        x + (size_t)row0[e] * D + cgrp * 4);
                    acc0.x += v.x; acc0.y += v.y; acc0.z += v.z; acc0.w += v.w;
                }
                if (has1 && e < m1) {
                    float4 v = *reinterpret_cast<const float4*>(
                        x + (size_t)row1[e] * D + cgrp * 4);
                    acc1.x += v.x; acc1.y += v.y; acc1.z += v.z; acc1.w += v.w;
                }
            }
        }

        // Butterfly over the 4 edge subgroups -> every lane has full sums.
#pragma unroll
        for (int off = 8; off <= 16; off <<= 1) {
            acc0.x += __shfl_xor_sync(0xffffffffu, acc0.x, off);
            acc0.y += __shfl_xor_sync(0xffffffffu, acc0.y, off);
            acc0.z += __shfl_xor_sync(0xffffffffu, acc0.z, off);
            acc0.w += __shfl_xor_sync(0xffffffffu, acc0.w, off);
            acc1.x += __shfl_xor_sync(0xffffffffu, acc1.x, off);
            acc1.y += __shfl_xor_sync(0xffffffffu, acc1.y, off);
            acc1.z += __shfl_xor_sync(0xffffffffu, acc1.z, off);
            acc1.w += __shfl_xor_sync(0xffffffffu, acc1.w, off);
        }

        float inv0 = 1.0f / fmaxf((float)deg0, 1.0f);
        float inv1 = 1.0f / fmaxf((float)deg1, 1.0f);

        // Stage mean rows in smem (lanes 0-7: node0, lanes 8-15: node1).
        if (lane < 8) {
            *reinterpret_cast<float4*>(&sm[wIn][0][cgrp * 4]) =
                make_float4(acc0.x * inv0, acc0.y * inv0, acc0.z * inv0, acc0.w * inv0);
        } else if (lane < 16) {
            *reinterpret_cast<float4*>(&sm[wIn][1][cgrp * 4]) =
                make_float4(acc1.x * inv1, acc1.y * inv1, acc1.z * inv1, acc1.w * inv1);
        }
        __syncwarp();

        // GEMV phase: lane = output column.
        float o0 = pre[(size_t)node0 * D + lane];
        float o1 = has1 ? pre[(size_t)node1 * D + lane] : 0.0f;
#pragma unroll
        for (int q = 0; q < D / 4; q++) {
            float4 m0 = *reinterpret_cast<const float4*>(&sm[wIn][0][q * 4]);
            float4 m1 = *reinterpret_cast<const float4*>(&sm[wIn][1][q * 4]);
            o0 = fmaf(m0.x, wl[4 * q + 0], o0);
            o0 = fmaf(m0.y, wl[4 * q + 1], o0);
            o0 = fmaf(m0.z, wl[4 * q + 2], o0);
            o0 = fmaf(m0.w, wl[4 * q + 3], o0);
            o1 = fmaf(m1.x, wl[4 * q + 0], o1);
            o1 = fmaf(m1.y, wl[4 * q + 1], o1);
            o1 = fmaf(m1.z, wl[4 * q + 2], o1);
            o1 = fmaf(m1.w, wl[4 * q + 3], o1);
        }
        out[(size_t)node0 * D + lane] = fmaxf(o0, 0.0f);
        if (has1) out[(size_t)node1 * D + lane] = fmaxf(o1, 0.0f);
        __syncwarp();   // protect smem reuse next iteration
    }
}

// ---------------------------------------------------------------------------
extern "C" void kernel_launch(void* const* d_in, const int* in_sizes, int n_in,
                              void* d_out, int out_size) {
    const float* x = (const float*)d_in[0];
    const int* edge_index = (const int*)d_in[1];   // int32 (JAX x64 disabled)
    const float* W1l = (const float*)d_in[2];
    const float* W1r = (const float*)d_in[3];
    const float* b1  = (const float*)d_in[4];
    const float* W2l = (const float*)d_in[5];
    const float* W2r = (const float*)d_in[6];
    const float* b2  = (const float*)d_in[7];
    float* out = (float*)d_out;

    const int E = in_sizes[1] / 2;
    const int N = N_NODES;
    const int* src = edge_index;
    const int* dst = edge_index + E;

    float* pre; cudaGetSymbolAddress((void**)&pre, g_pre);
    float* h1;  cudaGetSymbolAddress((void**)&h1, g_h1);
    int* cnt;   cudaGetSymbolAddress((void**)&cnt, g_cnt);
    int* ell;   cudaGetSymbolAddress((void**)&ell, g_ell);

    const int TPB = 256;
    const int nb_fill = ((E + 1) / 2 + TPB - 1) / TPB;   // 2 edges/thread
    const int nb_fused = 1184;                           // grid-stride pairs
    const int nb_mv = 600;                               // grid-stride (proven)

    // ---- ELL build (reused by both layers) ----
    cudaMemsetAsync(cnt, 0, N * sizeof(int));
    ell_fill_kernel<<<nb_fill, TPB>>>(src, dst, cnt, ell, E);

    // ---- Layer 1 ----
    rootmv_kernel<<<nb_mv, TPB>>>(x, W1r, b1, pre, N);
    fused_kernel<<<nb_fused, TPB>>>(x, cnt, ell, W1l, pre, h1, N);

    // ---- Layer 2 ----
    rootmv_kernel<<<nb_mv, TPB>>>(h1, W2r, b2, pre, N);
    fused_kernel<<<nb_fused, TPB>>>(h1, cnt, ell, W2l, pre, out, N);
}

// round 10
// speedup vs baseline: 1.3938x; 1.3938x over previous
#include <cuda_runtime.h>
#include <cuda_bf16.h>

#define N_NODES 100000
#define D 32
#define ELL_W 64   // max in-degree; deg ~ Poisson(16), P(>=64) ~ 1e-17 per node

// ------------------------- scratch (__device__ globals) --------------------
__device__ float g_h1[N_NODES * D];         // layer-1 output
__device__ int   g_cnt[N_NODES];            // per-node fill cursor == in-degree
__device__ int   g_ell[N_NODES * ELL_W];    // ELL src-index table

// ---------------------------------------------------------------------------
// Edge-parallel ELL fill, 4 edges per thread (independent chains, int4 loads).
__global__ void ell_fill_kernel(const int* __restrict__ src,
                                const int* __restrict__ dst,
                                int* __restrict__ cnt,
                                int* __restrict__ ell, int E) {
    int t = blockIdx.x * blockDim.x + threadIdx.x;
    int e0 = t * 4;
    if (e0 + 3 < E) {
        int4 s = *reinterpret_cast<const int4*>(src + e0);
        int4 d = *reinterpret_cast<const int4*>(dst + e0);
        int sl0 = atomicAdd(&cnt[d.x], 1);
        int sl1 = atomicAdd(&cnt[d.y], 1);
        int sl2 = atomicAdd(&cnt[d.z], 1);
        int sl3 = atomicAdd(&cnt[d.w], 1);
        if (sl0 < ELL_W) ell[d.x * ELL_W + sl0] = s.x;
        if (sl1 < ELL_W) ell[d.y * ELL_W + sl1] = s.y;
        if (sl2 < ELL_W) ell[d.z * ELL_W + sl2] = s.z;
        if (sl3 < ELL_W) ell[d.w * ELL_W + sl3] = s.w;
    } else {
        for (int e = e0; e < E; e++) {
            int sv = src[e], dv = dst[e];
            int slot = atomicAdd(&cnt[dv], 1);
            if (slot < ELL_W) ell[dv * ELL_W + slot] = sv;
        }
    }
}

// ---------------------------------------------------------------------------
// Fully fused SAGE layer:
//   out[n] = relu( mean_{s in N(n)} x[s] @ Wl + b + x[n] @ Wr )
// TWO nodes per warp-iteration, grid-stride over node pairs.
// Phase 1 (gather): proven R8 scheme — 4 edges per LDG.128, butterfly reduce.
// Phase 2 (stage):  mean rows + root rows staged in smem (root rows loaded
//                   coalesced by lanes 0-15, NOT via broadcast LDG).
// Phase 3 (GEMV):   lane = output column; Wl,Wr columns in registers; inputs
//                   read as LDS.128 broadcasts from smem.
__global__ void __launch_bounds__(256) fused_layer_kernel(
        const float* __restrict__ x,
        const int* __restrict__ cnt,
        const int* __restrict__ ell,
        const float* __restrict__ Wl,
        const float* __restrict__ Wr,
        const float* __restrict__ b,
        float* __restrict__ out, int n) {
    __shared__ float sm[8][2][D];   // [warp][node-in-pair][col] : mean rows
    __shared__ float sr[8][2][D];   // [warp][node-in-pair][col] : root rows

    int lane = threadIdx.x & 31;
    int wIn = threadIdx.x >> 5;
    int warp = blockIdx.x * 8 + wIn;
    int nWarps = gridDim.x * 8;
    int nPairs = (n + 1) >> 1;

    int egrp = lane >> 3;   // 0..3 : edge within a 4-edge chunk
    int cgrp = lane & 7;    // 0..7 : float4 column group

    // Weight columns in registers (lane = output column).
    float wl[D], wr[D];
#pragma unroll
    for (int k = 0; k < D; k++) {
        wl[k] = Wl[k * D + lane];
        wr[k] = Wr[k * D + lane];
    }
    float bias = b[lane];

    for (int p = warp; p < nPairs; p += nWarps) {
        int node0 = p * 2;
        int node1 = node0 + 1;
        bool has1 = (node1 < n);

        int deg0 = cnt[node0];
        int deg1 = has1 ? cnt[node1] : 0;
        int m0 = deg0 < ELL_W ? deg0 : ELL_W;
        int m1 = deg1 < ELL_W ? deg1 : ELL_W;
        const int* row0 = ell + node0 * ELL_W;
        const int* row1 = ell + node1 * ELL_W;

        // ---- Phase 2a: coalesced root-row load (issue early, consumed late)
        int rnode = (lane < 8) ? node0 : node1;
        float4 rootv = make_float4(0.f, 0.f, 0.f, 0.f);
        if (lane < 16 && (lane < 8 || has1)) {
            rootv = *reinterpret_cast<const float4*>(
                x + (size_t)rnode * D + cgrp * 4);
        }

        // ---- Phase 1: gather
        int id0[8], id1[8];
#pragma unroll
        for (int c = 0; c < 8; c++) {
            int e = c * 4 + egrp;
            id0[c] = (e < m0) ? row0[e] : -1;
            id1[c] = (has1 && e < m1) ? row1[e] : -1;
        }

        float4 acc0 = make_float4(0.f, 0.f, 0.f, 0.f);
        float4 acc1 = make_float4(0.f, 0.f, 0.f, 0.f);
#pragma unroll
        for (int c = 0; c < 8; c++) {
            if (id0[c] >= 0) {
                float4 v = *reinterpret_cast<const float4*>(
                    x + (size_t)id0[c] * D + cgrp * 4);
                acc0.x += v.x; acc0.y += v.y; acc0.z += v.z; acc0.w += v.w;
            }
            if (id1[c] >= 0) {
                float4 v = *reinterpret_cast<const float4*>(
                    x + (size_t)id1[c] * D + cgrp * 4);
                acc1.x += v.x; acc1.y += v.y; acc1.z += v.z; acc1.w += v.w;
            }
        }
        if (m0 > 32 || m1 > 32) {   // rare tail: deg > 32
#pragma unroll
            for (int c = 0; c < 8; c++) {
                int e = 32 + c * 4 + egrp;
                if (e < m0) {
                    float4 v = *reinterpret_cast<const float4*>(
                        x + (size_t)row0[e] * D + cgrp * 4);
                    acc0.x += v.x; acc0.y += v.y; acc0.z += v.z; acc0.w += v.w;
                }
                if (has1 && e < m1) {
                    float4 v = *reinterpret_cast<const float4*>(
                        x + (size_t)row1[e] * D + cgrp * 4);
                    acc1.x += v.x; acc1.y += v.y; acc1.z += v.z; acc1.w += v.w;
                }
            }
        }

        // Butterfly over the 4 edge subgroups -> every lane has full sums.
#pragma unroll
        for (int off = 8; off <= 16; off <<= 1) {
            acc0.x += __shfl_xor_sync(0xffffffffu, acc0.x, off);
            acc0.y += __shfl_xor_sync(0xffffffffu, acc0.y, off);
            acc0.z += __shfl_xor_sync(0xffffffffu, acc0.z, off);
            acc0.w += __shfl_xor_sync(0xffffffffu, acc0.w, off);
            acc1.x += __shfl_xor_sync(0xffffffffu, acc1.x, off);
            acc1.y += __shfl_xor_sync(0xffffffffu, acc1.y, off);
            acc1.z += __shfl_xor_sync(0xffffffffu, acc1.z, off);
            acc1.w += __shfl_xor_sync(0xffffffffu, acc1.w, off);
        }

        float inv0 = 1.0f / fmaxf((float)deg0, 1.0f);
        float inv1 = 1.0f / fmaxf((float)deg1, 1.0f);

        // ---- Phase 2b: stage mean rows + root rows in smem
        if (lane < 8) {
            *reinterpret_cast<float4*>(&sm[wIn][0][cgrp * 4]) =
                make_float4(acc0.x * inv0, acc0.y * inv0,
                            acc0.z * inv0, acc0.w * inv0);
            *reinterpret_cast<float4*>(&sr[wIn][0][cgrp * 4]) = rootv;
        } else if (lane < 16) {
            *reinterpret_cast<float4*>(&sm[wIn][1][cgrp * 4]) =
                make_float4(acc1.x * inv1, acc1.y * inv1,
                            acc1.z * inv1, acc1.w * inv1);
            *reinterpret_cast<float4*>(&sr[wIn][1][cgrp * 4]) = rootv;
        }
        __syncwarp();

        // ---- Phase 3: GEMV, lane = output column
        float o0 = bias;
        float o1 = bias;
#pragma unroll
        for (int q = 0; q < D / 4; q++) {
            float4 mA = *reinterpret_cast<const float4*>(&sm[wIn][0][q * 4]);
            float4 mB = *reinterpret_cast<const float4*>(&sm[wIn][1][q * 4]);
            float4 rA = *reinterpret_cast<const float4*>(&sr[wIn][0][q * 4]);
            float4 rB = *reinterpret_cast<const float4*>(&sr[wIn][1][q * 4]);
            o0 = fmaf(mA.x, wl[4 * q + 0], o0);
            o0 = fmaf(mA.y, wl[4 * q + 1], o0);
            o0 = fmaf(mA.z, wl[4 * q + 2], o0);
            o0 = fmaf(mA.w, wl[4 * q + 3], o0);
            o0 = fmaf(rA.x, wr[4 * q + 0], o0);
            o0 = fmaf(rA.y, wr[4 * q + 1], o0);
            o0 = fmaf(rA.z, wr[4 * q + 2], o0);
            o0 = fmaf(rA.w, wr[4 * q + 3], o0);
            o1 = fmaf(mB.x, wl[4 * q + 0], o1);
            o1 = fmaf(mB.y, wl[4 * q + 1], o1);
            o1 = fmaf(mB.z, wl[4 * q + 2], o1);
            o1 = fmaf(mB.w, wl[4 * q + 3], o1);
            o1 = fmaf(rB.x, wr[4 * q + 0], o1);
            o1 = fmaf(rB.y, wr[4 * q + 1], o1);
            o1 = fmaf(rB.z, wr[4 * q + 2], o1);
            o1 = fmaf(rB.w, wr[4 * q + 3], o1);
        }
        out[(size_t)node0 * D + lane] = fmaxf(o0, 0.0f);
        if (has1) out[(size_t)node1 * D + lane] = fmaxf(o1, 0.0f);
        __syncwarp();   // protect smem reuse next iteration
    }
}

// ---------------------------------------------------------------------------
extern "C" void kernel_launch(void* const* d_in, const int* in_sizes, int n_in,
                              void* d_out, int out_size) {
    const float* x = (const float*)d_in[0];
    const int* edge_index = (const int*)d_in[1];   // int32 (JAX x64 disabled)
    const float* W1l = (const float*)d_in[2];
    const float* W1r = (const float*)d_in[3];
    const float* b1  = (const float*)d_in[4];
    const float* W2l = (const float*)d_in[5];
    const float* W2r = (const float*)d_in[6];
    const float* b2  = (const float*)d_in[7];
    float* out = (float*)d_out;

    const int E = in_sizes[1] / 2;
    const int N = N_NODES;
    const int* src = edge_index;
    const int* dst = edge_index + E;

    float* h1;  cudaGetSymbolAddress((void**)&h1, g_h1);
    int* cnt;   cudaGetSymbolAddress((void**)&cnt, g_cnt);
    int* ell;   cudaGetSymbolAddress((void**)&ell, g_ell);

    const int TPB = 256;
    const int nb_fill = ((E + 3) / 4 + TPB - 1) / TPB;   // 4 edges/thread
    const int nb_fused = 1184;                           // grid-stride pairs

    // ---- ELL build (reused by both layers) ----
    cudaMemsetAsync(cnt, 0, N * sizeof(int));
    ell_fill_kernel<<<nb_fill, TPB>>>(src, dst, cnt, ell, E);

    // ---- Layer 1 ----
    fused_layer_kernel<<<nb_fused, TPB>>>(x, cnt, ell, W1l, W1r, b1, h1, N);

    // ---- Layer 2 ----
    fused_layer_kernel<<<nb_fused, TPB>>>(h1, cnt, ell, W2l, W2r, b2, out, N);
}